// round 5
// baseline (speedup 1.0000x reference)
#include <cuda_runtime.h>
#include <cstdint>

// Bayesian MLP: B=1024, IN=256, HID=512, OUT=2.
// JAX threefry2x32, PARTITIONABLE mode (jax_threefry_partitionable=True,
// default in modern JAX):
//   split  (foldlike): nk[i] = threefry(key, (0, i)) -> (w0, w1) is the new key
//   random_bits 32   : bits[j] = w0 ^ w1 of threefry(key, (hi32(j), lo32(j)))
//                      (all arrays here have < 2^32 elements -> hi = 0)

#define BATCH 1024
#define INF_  256
#define HIDF  512

// ---------------------------------------------------------------------------
// Compile-time threefry2x32 (JAX variant, 20 rounds) for subkey derivation
// ---------------------------------------------------------------------------
constexpr uint32_t rotl_c(uint32_t x, int r) { return (x << r) | (x >> (32 - r)); }

constexpr unsigned long long ctf(uint32_t k0, uint32_t k1, uint32_t x0, uint32_t x1) {
    uint32_t ks[3] = {k0, k1, k0 ^ k1 ^ 0x1BD11BDAu};
    const int R[5][4] = {{13,15,26,6},{17,29,16,24},{13,15,26,6},{17,29,16,24},{13,15,26,6}};
    x0 += ks[0]; x1 += ks[1];
    for (int g = 0; g < 5; ++g) {
        for (int r = 0; r < 4; ++r) { x0 += x1; x1 = rotl_c(x1, R[g][r]); x1 ^= x0; }
        x0 += ks[(g + 1) % 3];
        x1 += ks[(g + 2) % 3] + (uint32_t)(g + 1);
    }
    return ((unsigned long long)x1 << 32) | x0;   // low = word0 (x0-lane), high = word1
}

// jax.random.key(42) -> (0, 42). Foldlike split(key, 4):
// nk[i] = threefry((0,42), counter (x0=hi=0, x1=lo=i)); new key = (word0, word1)
constexpr unsigned long long N0 = ctf(0u, 42u, 0u, 0u);   // nk0: eps_w1
constexpr unsigned long long N1 = ctf(0u, 42u, 0u, 1u);   // nk1: eps_b1
constexpr unsigned long long N2 = ctf(0u, 42u, 0u, 2u);   // nk2: eps_w2
constexpr unsigned long long N3 = ctf(0u, 42u, 0u, 3u);   // nk3: eps_b2

constexpr uint32_t KW1_0 = (uint32_t)(N0 & 0xffffffffu);
constexpr uint32_t KW1_1 = (uint32_t)(N0 >> 32);
constexpr uint32_t KB1_0 = (uint32_t)(N1 & 0xffffffffu);
constexpr uint32_t KB1_1 = (uint32_t)(N1 >> 32);
constexpr uint32_t KW2_0 = (uint32_t)(N2 & 0xffffffffu);
constexpr uint32_t KW2_1 = (uint32_t)(N2 >> 32);
constexpr uint32_t KB2_0 = (uint32_t)(N3 & 0xffffffffu);
constexpr uint32_t KB2_1 = (uint32_t)(N3 >> 32);

// ---------------------------------------------------------------------------
// Device threefry2x32; returns folded 32-bit output word0 ^ word1
// (partitionable random_bits for bit_width=32)
// ---------------------------------------------------------------------------
#define TF_ROUND(r) { x0 += x1; x1 = __funnelshift_l(x1, x1, (r)); x1 ^= x0; }

__device__ __forceinline__ uint32_t tf_fold(uint32_t k0, uint32_t k1, uint32_t j) {
    const uint32_t ks2 = k0 ^ k1 ^ 0x1BD11BDAu;
    uint32_t x0 = k0;            // counter hi word is 0 for all arrays here
    uint32_t x1 = j + k1;
    TF_ROUND(13) TF_ROUND(15) TF_ROUND(26) TF_ROUND(6)
    x0 += k1;  x1 += ks2 + 1u;
    TF_ROUND(17) TF_ROUND(29) TF_ROUND(16) TF_ROUND(24)
    x0 += ks2; x1 += k0 + 2u;
    TF_ROUND(13) TF_ROUND(15) TF_ROUND(26) TF_ROUND(6)
    x0 += k0;  x1 += k1 + 3u;
    TF_ROUND(17) TF_ROUND(29) TF_ROUND(16) TF_ROUND(24)
    x0 += k1;  x1 += ks2 + 4u;
    TF_ROUND(13) TF_ROUND(15) TF_ROUND(26) TF_ROUND(6)
    x0 += ks2; x1 += k0 + 5u;
    return x0 ^ x1;
}

// bits -> uniform in [nextafter(-1,0), 1) -> sqrt(2)*erfinv  (matches JAX/XLA)
__device__ __forceinline__ float bits_to_normal(uint32_t bits) {
    const float LO = -0.99999994f;  // nextafter(-1, 0) in f32
    float f = __uint_as_float((bits >> 9) | 0x3f800000u) - 1.0f;  // [0,1)
    float u = fmaxf(fmaf(f, 2.0f, LO), LO);   // (hi-lo) rounds to exactly 2.0f
    // Giles single-precision erfinv (identical coefficients to XLA ErfInv32)
    float w = -__logf(fmaf(u, -u, 1.0f));
    float p;
    if (w < 5.0f) {
        w -= 2.5f;
        p =              2.81022636e-08f;
        p = fmaf(p, w,   3.43273939e-07f);
        p = fmaf(p, w,  -3.5233877e-06f);
        p = fmaf(p, w,  -4.39150654e-06f);
        p = fmaf(p, w,   0.00021858087f);
        p = fmaf(p, w,  -0.00125372503f);
        p = fmaf(p, w,  -0.00417768164f);
        p = fmaf(p, w,   0.246640727f);
        p = fmaf(p, w,   1.50140941f);
    } else {
        w = sqrtf(w) - 3.0f;
        p =             -0.000200214257f;
        p = fmaf(p, w,   0.000100950558f);
        p = fmaf(p, w,   0.00134934322f);
        p = fmaf(p, w,  -0.00367342844f);
        p = fmaf(p, w,   0.00573950773f);
        p = fmaf(p, w,  -0.0076224613f);
        p = fmaf(p, w,   0.00943887047f);
        p = fmaf(p, w,   1.00167406f);
        p = fmaf(p, w,   2.83297682f);
    }
    return 1.41421356237f * (p * u);
}

// ---------------------------------------------------------------------------
// Scratch (no cudaMalloc allowed)
// ---------------------------------------------------------------------------
__device__ float g_w1_std[HIDF * INF_];
__device__ float g_b1_std[HIDF];
__device__ float g_w2_std[2 * HIDF];
__device__ float g_b2_std[2];
__device__ float g_h[BATCH * HIDF];

// ---------------------------------------------------------------------------
// Prep: std = exp(0.5 * logvar)
// ---------------------------------------------------------------------------
__global__ void prep_kernel(const float* __restrict__ w1lv, const float* __restrict__ b1lv,
                            const float* __restrict__ w2lv, const float* __restrict__ b2lv) {
    int i = blockIdx.x * blockDim.x + threadIdx.x;        // exactly 131072 threads
    g_w1_std[i] = expf(0.5f * w1lv[i]);
    if (i < HIDF)     g_b1_std[i] = expf(0.5f * b1lv[i]);
    if (i < 2 * HIDF) g_w2_std[i] = expf(0.5f * w2lv[i]);
    if (i < 2)        g_b2_std[i] = expf(0.5f * b2lv[i]);
}

// ---------------------------------------------------------------------------
// Layer 1: one warp per (b, o); lanes stride i.
// eps_w1 flat index j = (b*HID + o)*IN + i; bits = fold(threefry(nk0, (0, j))).
// eps_b1 flat index  = b*HID + o.
// ---------------------------------------------------------------------------
__global__ void __launch_bounds__(256) layer1_kernel(const float* __restrict__ x,
                                                     const float* __restrict__ w1mu,
                                                     const float* __restrict__ b1mu) {
    const unsigned wid  = blockIdx.x * 8u + (threadIdx.x >> 5);   // [0, 524288)
    const int      lane = threadIdx.x & 31;
    const int      b    = (int)(wid >> 9);     // [0, 1024)
    const int      o    = (int)(wid & 511u);   // [0, 512)

    const float* __restrict__ mu = w1mu     + o * INF_;
    const float* __restrict__ sd = g_w1_std + o * INF_;
    const float* __restrict__ xr = x + b * INF_;

    const unsigned jbase = (unsigned)(b * HIDF + o) * (unsigned)INF_;

    float s = 0.0f;
#pragma unroll 4
    for (int t = 0; t < 8; ++t) {
        const int      i = lane + t * 32;
        const unsigned j = jbase + (unsigned)i;
        const float eps = bits_to_normal(tf_fold(KW1_0, KW1_1, j));
        s = fmaf(fmaf(sd[i], eps, mu[i]), xr[i], s);
    }
#pragma unroll
    for (int off = 16; off; off >>= 1)
        s += __shfl_down_sync(0xffffffffu, s, off);

    if (lane == 0) {
        const unsigned tb = (unsigned)(b * HIDF + o);
        const float eps_b = bits_to_normal(tf_fold(KB1_0, KB1_1, tb));
        const float h = s + fmaf(g_b1_std[o], eps_b, b1mu[o]);
        g_h[tb] = fmaxf(h, 0.0f);
    }
}

// ---------------------------------------------------------------------------
// Layer 2 + epilogue: one warp per (b, o2).
// eps_w2 flat index j = (b*OUT + o2)*HID + k; eps_b2 index = b*OUT + o2.
// Output layout: mean[0..1024) then var[1024..2048).
// ---------------------------------------------------------------------------
__global__ void __launch_bounds__(256) layer2_kernel(const float* __restrict__ w2mu,
                                                     const float* __restrict__ b2mu,
                                                     float* __restrict__ out) {
    const unsigned wid  = blockIdx.x * 8u + (threadIdx.x >> 5);   // [0, 2048)
    const int      lane = threadIdx.x & 31;
    const int      b    = (int)(wid >> 1);   // [0, 1024)
    const int      o2   = (int)(wid & 1u);

    const float* __restrict__ mu = w2mu     + o2 * HIDF;
    const float* __restrict__ sd = g_w2_std + o2 * HIDF;
    const float* __restrict__ hr = g_h + b * HIDF;

    const unsigned jbase = (unsigned)(b * 2 + o2) * (unsigned)HIDF;

    float s = 0.0f;
#pragma unroll 4
    for (int t = 0; t < 16; ++t) {
        const int      k = lane + t * 32;
        const unsigned j = jbase + (unsigned)k;
        const float eps = bits_to_normal(tf_fold(KW2_0, KW2_1, j));
        s = fmaf(fmaf(sd[k], eps, mu[k]), hr[k], s);
    }
#pragma unroll
    for (int off = 16; off; off >>= 1)
        s += __shfl_down_sync(0xffffffffu, s, off);

    if (lane == 0) {
        const unsigned tb = (unsigned)(b * 2 + o2);
        const float eps_b = bits_to_normal(tf_fold(KB2_0, KB2_1, tb));
        const float v = s + fmaf(g_b2_std[o2], eps_b, b2mu[o2]);
        if (o2 == 0) out[b] = v;                                  // mean
        else         out[BATCH + b] = fmaxf(expf(v), 1e-6f);      // var
    }
}

// ---------------------------------------------------------------------------
extern "C" void kernel_launch(void* const* d_in, const int* in_sizes, int n_in,
                              void* d_out, int out_size) {
    const float* x     = (const float*)d_in[0];
    const float* w1mu  = (const float*)d_in[1];
    const float* w1lv  = (const float*)d_in[2];
    const float* b1mu  = (const float*)d_in[3];
    const float* b1lv  = (const float*)d_in[4];
    const float* w2mu  = (const float*)d_in[5];
    const float* w2lv  = (const float*)d_in[6];
    const float* b2mu  = (const float*)d_in[7];
    const float* b2lv  = (const float*)d_in[8];
    float* out = (float*)d_out;

    prep_kernel<<<512, 256>>>(w1lv, b1lv, w2lv, b2lv);
    layer1_kernel<<<65536, 256>>>(x, w1mu, b1mu);
    layer2_kernel<<<256, 256>>>(w2mu, b2mu, out);
}

// round 11
// speedup vs baseline: 1.0669x; 1.0669x over previous
#include <cuda_runtime.h>
#include <cstdint>

// Bayesian MLP: B=1024, IN=256, HID=512, OUT=2.
// JAX threefry2x32, PARTITIONABLE mode:
//   split  (foldlike): nk[i] = threefry(key, (0, i)) -> (w0, w1) is the new key
//   random_bits 32   : bits[j] = w0 ^ w1 of threefry(key, (0, j))

#define BATCH 1024
#define INF_  256
#define HIDF  512

// ---------------------------------------------------------------------------
// Compile-time threefry2x32 for subkey derivation
// ---------------------------------------------------------------------------
constexpr uint32_t rotl_c(uint32_t x, int r) { return (x << r) | (x >> (32 - r)); }

constexpr unsigned long long ctf(uint32_t k0, uint32_t k1, uint32_t x0, uint32_t x1) {
    uint32_t ks[3] = {k0, k1, k0 ^ k1 ^ 0x1BD11BDAu};
    const int R[5][4] = {{13,15,26,6},{17,29,16,24},{13,15,26,6},{17,29,16,24},{13,15,26,6}};
    x0 += ks[0]; x1 += ks[1];
    for (int g = 0; g < 5; ++g) {
        for (int r = 0; r < 4; ++r) { x0 += x1; x1 = rotl_c(x1, R[g][r]); x1 ^= x0; }
        x0 += ks[(g + 1) % 3];
        x1 += ks[(g + 2) % 3] + (uint32_t)(g + 1);
    }
    return ((unsigned long long)x1 << 32) | x0;
}

constexpr unsigned long long N0 = ctf(0u, 42u, 0u, 0u);   // nk0: eps_w1
constexpr unsigned long long N1 = ctf(0u, 42u, 0u, 1u);   // nk1: eps_b1
constexpr unsigned long long N2 = ctf(0u, 42u, 0u, 2u);   // nk2: eps_w2
constexpr unsigned long long N3 = ctf(0u, 42u, 0u, 3u);   // nk3: eps_b2

constexpr uint32_t KW1_0 = (uint32_t)(N0 & 0xffffffffu);
constexpr uint32_t KW1_1 = (uint32_t)(N0 >> 32);
constexpr uint32_t KB1_0 = (uint32_t)(N1 & 0xffffffffu);
constexpr uint32_t KB1_1 = (uint32_t)(N1 >> 32);
constexpr uint32_t KW2_0 = (uint32_t)(N2 & 0xffffffffu);
constexpr uint32_t KW2_1 = (uint32_t)(N2 >> 32);
constexpr uint32_t KB2_0 = (uint32_t)(N3 & 0xffffffffu);
constexpr uint32_t KB2_1 = (uint32_t)(N3 >> 32);

// ---------------------------------------------------------------------------
// add on the FMA pipe (IMAD) to relieve the alu pipe (SHF/LOP3 are alu-only)
// ---------------------------------------------------------------------------
__device__ __forceinline__ uint32_t imad1(uint32_t a, uint32_t b) {
    uint32_t d;
    asm("mad.lo.u32 %0, %1, 1, %2;" : "=r"(d) : "r"(a), "r"(b));
    return d;
}

// round: add on fma pipe, rotate+xor on alu pipe
#define TF_ROUND(r) { x0 = imad1(x0, x1); x1 = __funnelshift_l(x1, x1, (r)); x1 ^= x0; }

__device__ __forceinline__ uint32_t tf_fold(uint32_t k0, uint32_t k1, uint32_t j) {
    const uint32_t ks2 = k0 ^ k1 ^ 0x1BD11BDAu;
    uint32_t x0 = k0;                 // counter hi word is 0
    uint32_t x1 = j + k1;
    TF_ROUND(13) TF_ROUND(15) TF_ROUND(26) TF_ROUND(6)
    x0 += k1;  x1 = imad1(x1, ks2 + 1u);
    TF_ROUND(17) TF_ROUND(29) TF_ROUND(16) TF_ROUND(24)
    x0 += ks2; x1 = imad1(x1, k0 + 2u);
    TF_ROUND(13) TF_ROUND(15) TF_ROUND(26) TF_ROUND(6)
    x0 += k0;  x1 = imad1(x1, k1 + 3u);
    TF_ROUND(17) TF_ROUND(29) TF_ROUND(16) TF_ROUND(24)
    x0 += k1;  x1 = imad1(x1, ks2 + 4u);
    TF_ROUND(13) TF_ROUND(15) TF_ROUND(26) TF_ROUND(6)
    x0 += ks2; x1 = imad1(x1, k0 + 5u);
    return x0 ^ x1;
}

// bits -> uniform in [nextafter(-1,0), 1) -> sqrt(2)*erfinv  (matches JAX/XLA)
__device__ __forceinline__ float bits_to_normal(uint32_t bits) {
    const float LO = -0.99999994f;
    float f = __uint_as_float((bits >> 9) | 0x3f800000u) - 1.0f;
    float u = fmaxf(fmaf(f, 2.0f, LO), LO);
    float w = -__logf(fmaf(u, -u, 1.0f));
    float p;
    if (w < 5.0f) {
        w -= 2.5f;
        p =              2.81022636e-08f;
        p = fmaf(p, w,   3.43273939e-07f);
        p = fmaf(p, w,  -3.5233877e-06f);
        p = fmaf(p, w,  -4.39150654e-06f);
        p = fmaf(p, w,   0.00021858087f);
        p = fmaf(p, w,  -0.00125372503f);
        p = fmaf(p, w,  -0.00417768164f);
        p = fmaf(p, w,   0.246640727f);
        p = fmaf(p, w,   1.50140941f);
    } else {
        w = sqrtf(w) - 3.0f;
        p =             -0.000200214257f;
        p = fmaf(p, w,   0.000100950558f);
        p = fmaf(p, w,   0.00134934322f);
        p = fmaf(p, w,  -0.00367342844f);
        p = fmaf(p, w,   0.00573950773f);
        p = fmaf(p, w,  -0.0076224613f);
        p = fmaf(p, w,   0.00943887047f);
        p = fmaf(p, w,   1.00167406f);
        p = fmaf(p, w,   2.83297682f);
    }
    return 1.41421356237f * (p * u);
}

// ---------------------------------------------------------------------------
// Scratch (no cudaMalloc allowed)
// ---------------------------------------------------------------------------
__device__ float g_w1_std[HIDF * INF_];
__device__ float g_b1_std[HIDF];
__device__ float g_w2_std[2 * HIDF];
__device__ float g_b2_std[2];
__device__ float g_h[BATCH * HIDF];

// ---------------------------------------------------------------------------
// Prep: std = exp(0.5 * logvar)
// ---------------------------------------------------------------------------
__global__ void prep_kernel(const float* __restrict__ w1lv, const float* __restrict__ b1lv,
                            const float* __restrict__ w2lv, const float* __restrict__ b2lv) {
    int i = blockIdx.x * blockDim.x + threadIdx.x;        // exactly 131072 threads
    g_w1_std[i] = expf(0.5f * w1lv[i]);
    if (i < HIDF)     g_b1_std[i] = expf(0.5f * b1lv[i]);
    if (i < 2 * HIDF) g_w2_std[i] = expf(0.5f * w2lv[i]);
    if (i < 2)        g_b2_std[i] = expf(0.5f * b2lv[i]);
}

// ---------------------------------------------------------------------------
// Layer 1: one warp per (b, o); lane owns 8 contiguous i (float4 x2 loads).
// eps_w1 flat index j = (b*HID + o)*IN + i.  eps_b1 flat index = b*HID + o.
// ---------------------------------------------------------------------------
__global__ void __launch_bounds__(256) layer1_kernel(const float* __restrict__ x,
                                                     const float* __restrict__ w1mu,
                                                     const float* __restrict__ b1mu) {
    const unsigned wid  = blockIdx.x * 8u + (threadIdx.x >> 5);   // [0, 524288)
    const int      lane = threadIdx.x & 31;
    const int      b    = (int)(wid >> 9);     // [0, 1024)
    const int      o    = (int)(wid & 511u);   // [0, 512)

    const float4* __restrict__ mu4 = (const float4*)(w1mu     + o * INF_);
    const float4* __restrict__ sd4 = (const float4*)(g_w1_std + o * INF_);
    const float4* __restrict__ xr4 = (const float4*)(x + b * INF_);

    const float4 m0 = mu4[2 * lane], m1 = mu4[2 * lane + 1];
    const float4 s0 = sd4[2 * lane], s1 = sd4[2 * lane + 1];
    const float4 xa = xr4[2 * lane], xb = xr4[2 * lane + 1];

    const unsigned jb = (unsigned)(b * HIDF + o) * (unsigned)INF_ + (unsigned)(lane * 8);

    float acc = 0.0f;
#define L1T(sv, mv, xv, q) \
    acc = fmaf(fmaf((sv), bits_to_normal(tf_fold(KW1_0, KW1_1, jb + (q))), (mv)), (xv), acc);
    L1T(s0.x, m0.x, xa.x, 0u) L1T(s0.y, m0.y, xa.y, 1u)
    L1T(s0.z, m0.z, xa.z, 2u) L1T(s0.w, m0.w, xa.w, 3u)
    L1T(s1.x, m1.x, xb.x, 4u) L1T(s1.y, m1.y, xb.y, 5u)
    L1T(s1.z, m1.z, xb.z, 6u) L1T(s1.w, m1.w, xb.w, 7u)
#undef L1T

#pragma unroll
    for (int off = 16; off; off >>= 1)
        acc += __shfl_down_sync(0xffffffffu, acc, off);

    if (lane == 0) {
        const unsigned tb = (unsigned)(b * HIDF + o);
        const float eps_b = bits_to_normal(tf_fold(KB1_0, KB1_1, tb));
        const float h = acc + fmaf(g_b1_std[o], eps_b, b1mu[o]);
        g_h[tb] = fmaxf(h, 0.0f);
    }
}

// ---------------------------------------------------------------------------
// Layer 2 + epilogue: one warp per (b, o2); lane owns 16 contiguous k.
// eps_w2 flat index j = (b*OUT + o2)*HID + k; eps_b2 index = b*OUT + o2.
// Output layout: mean[0..1024) then var[1024..2048).
// ---------------------------------------------------------------------------
__global__ void __launch_bounds__(256) layer2_kernel(const float* __restrict__ w2mu,
                                                     const float* __restrict__ b2mu,
                                                     float* __restrict__ out) {
    const unsigned wid  = blockIdx.x * 8u + (threadIdx.x >> 5);   // [0, 2048)
    const int      lane = threadIdx.x & 31;
    const int      b    = (int)(wid >> 1);   // [0, 1024)
    const int      o2   = (int)(wid & 1u);

    const float4* __restrict__ mu4 = (const float4*)(w2mu     + o2 * HIDF);
    const float4* __restrict__ sd4 = (const float4*)(g_w2_std + o2 * HIDF);
    const float4* __restrict__ hr4 = (const float4*)(g_h + b * HIDF);

    const unsigned jb = (unsigned)(b * 2 + o2) * (unsigned)HIDF + (unsigned)(lane * 16);

    float acc = 0.0f;
#pragma unroll
    for (int c = 0; c < 4; ++c) {
        const float4 m = mu4[4 * lane + c];
        const float4 s = sd4[4 * lane + c];
        const float4 h = hr4[4 * lane + c];
        const unsigned j0 = jb + (unsigned)(c * 4);
        acc = fmaf(fmaf(s.x, bits_to_normal(tf_fold(KW2_0, KW2_1, j0 + 0u)), m.x), h.x, acc);
        acc = fmaf(fmaf(s.y, bits_to_normal(tf_fold(KW2_0, KW2_1, j0 + 1u)), m.y), h.y, acc);
        acc = fmaf(fmaf(s.z, bits_to_normal(tf_fold(KW2_0, KW2_1, j0 + 2u)), m.z), h.z, acc);
        acc = fmaf(fmaf(s.w, bits_to_normal(tf_fold(KW2_0, KW2_1, j0 + 3u)), m.w), h.w, acc);
    }

#pragma unroll
    for (int off = 16; off; off >>= 1)
        acc += __shfl_down_sync(0xffffffffu, acc, off);

    if (lane == 0) {
        const unsigned tb = (unsigned)(b * 2 + o2);
        const float eps_b = bits_to_normal(tf_fold(KB2_0, KB2_1, tb));
        const float v = acc + fmaf(g_b2_std[o2], eps_b, b2mu[o2]);
        if (o2 == 0) out[b] = v;                                  // mean
        else         out[BATCH + b] = fmaxf(expf(v), 1e-6f);      // var
    }
}

// ---------------------------------------------------------------------------
extern "C" void kernel_launch(void* const* d_in, const int* in_sizes, int n_in,
                              void* d_out, int out_size) {
    const float* x     = (const float*)d_in[0];
    const float* w1mu  = (const float*)d_in[1];
    const float* w1lv  = (const float*)d_in[2];
    const float* b1mu  = (const float*)d_in[3];
    const float* b1lv  = (const float*)d_in[4];
    const float* w2mu  = (const float*)d_in[5];
    const float* w2lv  = (const float*)d_in[6];
    const float* b2mu  = (const float*)d_in[7];
    const float* b2lv  = (const float*)d_in[8];
    float* out = (float*)d_out;

    prep_kernel<<<512, 256>>>(w1lv, b1lv, w2lv, b2lv);
    layer1_kernel<<<65536, 256>>>(x, w1mu, b1mu);
    layer2_kernel<<<256, 256>>>(w2mu, b2mu, out);
}